// round 8
// baseline (speedup 1.0000x reference)
#include <cuda_runtime.h>
#include <cstdint>

#define BB 64
#define NN 1024

// Output layout (flattened reference tuple, all float32):
#define OFF_DONE 0
#define OFF_NM   1
#define OFF_ADJ  (1 + BB*NN)
#define OFF_FA   (OFF_ADJ + (size_t)BB*NN*NN)
#define OFF_PT   (OFF_FA + BB)
#define OFF_STEP (OFF_PT + BB)

__device__ float g_fp[BB * NN];     // fpresent[b, i]
__device__ float g_dlast[NN];       // dist[:, N-1] contiguous
__device__ float g_nmlast[BB];      // new_mask[b, N-1] (for `done` reduction)

__global__ void k_prep(const float* __restrict__ inputs,
                       const float* __restrict__ dist,
                       const float* __restrict__ mask,
                       const float* __restrict__ ptime,
                       const int*   __restrict__ pres,
                       const int*   __restrict__ fut,
                       float* out)
{
    int b = blockIdx.x;
    int j = threadIdx.x;

    int   pa = pres[b];
    float pt = ptime[b];

    float4 in4 = *reinterpret_cast<const float4*>(inputs + ((size_t)(b * NN + j)) * 4);
    float op = in4.x, cl = in4.y, dur = in4.z;
    float T0 = inputs[3];

    float dlast  = dist[(size_t)j * NN + (NN - 1)];
    float arrive = dist[(size_t)pa * NN + j] + pt;
    float wait   = fmaxf(0.0f, op - arrive);
    float t      = arrive + wait;

    bool c1 = t <= cl;
    bool c2 = ((t + dur) + dlast) <= T0;

    float m = mask[b * NN + j];
    if (j == pa) m = 0.0f;
    float nm = (c1 && c2) ? m : 0.0f;

    float fpres = t + dur;

    out[OFF_NM + b * NN + j] = nm;
    g_fp[b * NN + j] = fpres;
    if (b == 0) g_dlast[j] = dlast;
    if (j == NN - 1) g_nmlast[b] = nm;

    int fb = fut[b];
    if (j == fb) out[OFF_PT + b] = fpres;
    if (j == 0) {
        out[OFF_FA + b]   = (float)fb;
        out[OFF_STEP + b] = 1.0f;
    }
}

// adj kernel — aligned-vector, rows OUTER / batches INNER so each dist row is
// loaded once and reused for BT batches. All BT batches' per-thread inputs are
// register-resident. Leftover scalars ({128w+0,1,2,127}) handled in a separate
// cheap pass by a rotating warp.
#define BT 4
#define RR 16

__global__ __launch_bounds__(256) void k_adj(const float* __restrict__ inputs,
                                             const float* __restrict__ dist,
                                             float* out)
{
    const int ITILES = NN / RR;                 // 64
    int itile = blockIdx.x & (ITILES - 1);
    int b0    = (blockIdx.x / ITILES) * BT;
    int i0    = itile * RR;
    int tid   = threadIdx.x;
    int warp  = tid >> 5;
    int lane  = tid & 31;
    int jw    = warp << 7;

    if (blockIdx.x == 0 && tid == 0) {
        float any = 0.0f;
#pragma unroll
        for (int b = 0; b < BB; b++) any = fmaxf(any, g_nmlast[b]);
        out[OFF_DONE] = (any > 0.0f) ? 0.0f : 1.0f;
    }

    int  ls  = (lane < 31) ? lane : 30;         // lane 31 mirrors lane 30
    bool act = (lane < 31);
    int  jb  = jw + 4 * ls + 3;                 // 4 output elements jb..jb+3
    int  j2a = jw + 4 * ls;                     // aligned dist load #1
    int  j2b = j2a + 4;                         // aligned dist load #2

    float dl[4];
#pragma unroll
    for (int e = 0; e < 4; e++) dl[e] = g_dlast[jb + e];

    const float* nm_base = out + OFF_NM;

    // ---- Register-resident inputs for all BT batches ----
    float op[BT][4], cl[BT][4], du[BT][4], nm[BT][4], Tb[BT];
#pragma unroll
    for (int bb = 0; bb < BT; bb++) {
        int b = b0 + bb;
#pragma unroll
        for (int e = 0; e < 4; e++) {
            float4 i4 = *reinterpret_cast<const float4*>(
                inputs + ((size_t)(b * NN + jb + e)) * 4);
            op[bb][e] = i4.x; cl[bb][e] = i4.y; du[bb][e] = i4.z;
        }
        float4 nm4 = *reinterpret_cast<const float4*>(nm_base + b * NN + jb);
        nm[bb][0] = nm4.x; nm[bb][1] = nm4.y; nm[bb][2] = nm4.z; nm[bb][3] = nm4.w;
        Tb[bb] = inputs[((size_t)b * NN) * 4 + 3];
    }

    // ---- Main: rows outer (dist loaded once), batches inner ----
#pragma unroll
    for (int r = 0; r < RR; r += 2) {
        int i_0 = i0 + r, i_1 = i0 + r + 1;
        const float* drow0 = dist + (size_t)i_0 * NN;
        const float* drow1 = dist + (size_t)i_1 * NN;

        // front-batched independent loads (MLP)
        float4 da0 = *reinterpret_cast<const float4*>(drow0 + j2a);
        float4 db0 = *reinterpret_cast<const float4*>(drow0 + j2b);
        float4 da1 = *reinterpret_cast<const float4*>(drow1 + j2a);
        float4 db1 = *reinterpret_cast<const float4*>(drow1 + j2b);
        float fp0[BT], fp1[BT];
#pragma unroll
        for (int bb = 0; bb < BT; bb++) {
            fp0[bb] = g_fp[(b0 + bb) * NN + i_0];
            fp1[bb] = g_fp[(b0 + bb) * NN + i_1];
        }

        float d0[4] = {da0.w, db0.x, db0.y, db0.z};
        float d1[4] = {da1.w, db1.x, db1.y, db1.z};

#pragma unroll
        for (int bb = 0; bb < BT; bb++) {
            int b = b0 + bb;
            float* orow0 = out + OFF_ADJ + ((size_t)(b * NN + i_0)) * NN;
            float* orow1 = out + OFF_ADJ + ((size_t)(b * NN + i_1)) * NN;

            float v0[4], v1[4];
#pragma unroll
            for (int e = 0; e < 4; e++) {
                {
                    float arr2 = d0[e] + fp0[bb];
                    float w    = fmaxf(0.0f, op[bb][e] - arr2);
                    float s    = arr2 + w;
                    bool a1 = s <= cl[bb][e];
                    bool a2 = ((s + du[bb][e]) + dl[e]) <= Tb[bb];
                    float x = (a1 && a2) ? nm[bb][e] : 0.0f;
                    if (jb + e == i_0) x = 1.0f;
                    v0[e] = x;
                }
                {
                    float arr2 = d1[e] + fp1[bb];
                    float w    = fmaxf(0.0f, op[bb][e] - arr2);
                    float s    = arr2 + w;
                    bool a1 = s <= cl[bb][e];
                    bool a2 = ((s + du[bb][e]) + dl[e]) <= Tb[bb];
                    float x = (a1 && a2) ? nm[bb][e] : 0.0f;
                    if (jb + e == i_1) x = 1.0f;
                    v1[e] = x;
                }
            }
            if (act) {
                *reinterpret_cast<float4*>(orow0 + jb) =
                    make_float4(v0[0], v0[1], v0[2], v0[3]);
                *reinterpret_cast<float4*>(orow1 + jb) =
                    make_float4(v1[0], v1[1], v1[2], v1[3]);
            }
        }
    }

    // ---- Leftover pass: j in {128w+0,1,2,127}, one lane each, rotating warp ----
    {
        int kw = lane >> 2, ke = lane & 3;
        int jL = (kw << 7) + ((ke == 3) ? 127 : ke);
        float dlL = g_dlast[jL];

#pragma unroll
        for (int bb = 0; bb < BT; bb++) {
            int b = b0 + bb;
            float4 iL = *reinterpret_cast<const float4*>(
                inputs + ((size_t)(b * NN + jL)) * 4);
            float nmL = nm_base[b * NN + jL];

#pragma unroll
            for (int r = 0; r < RR; r++) {
                if (warp != (r & 7)) continue;
                int i = i0 + r;
                float fp = g_fp[b * NN + i];
                float arr2 = __ldg(dist + (size_t)i * NN + jL) + fp;
                float w    = fmaxf(0.0f, iL.x - arr2);
                float s    = arr2 + w;
                bool a1 = s <= iL.y;
                bool a2 = ((s + iL.z) + dlL) <= Tb[bb];
                float x = (a1 && a2) ? nmL : 0.0f;
                if (jL == i) x = 1.0f;
                out[OFF_ADJ + ((size_t)(b * NN + i)) * NN + jL] = x;
            }
        }
    }
}

extern "C" void kernel_launch(void* const* d_in, const int* in_sizes, int n_in,
                              void* d_out, int out_size)
{
    const float* inputs = (const float*)d_in[0];   // (B, N, 4) f32
    const float* dist   = (const float*)d_in[1];   // (N, N)   f32
    const float* mask   = (const float*)d_in[2];   // (B, N)   f32
    const float* ptime  = (const float*)d_in[3];   // (B, 1)   f32
    const int*   pres   = (const int*)d_in[4];     // (B,)     i32
    const int*   fut    = (const int*)d_in[5];     // (B,)     i32
    float* out = (float*)d_out;

    k_prep<<<BB, NN>>>(inputs, dist, mask, ptime, pres, fut, out);
    k_adj<<<(NN / RR) * (BB / BT), 256>>>(inputs, dist, out);
}